// round 6
// baseline (speedup 1.0000x reference)
#include <cuda_runtime.h>
#include <cuda_fp16.h>
#include <cstdint>

#define NN 50000
#define RR 33
#define DD 1600
#define WSZ 16
#define CC 10
#define NRW 528
#define NRC 330
#define NRWP 576   // padded cols for GEMM (3 tiles of 192)

// ---- scratch (static device globals; allocation forbidden) ----
__device__ __half g_proj1[(size_t)NN * NRW];   // 52.8 MB
__device__ float  g_h1[NN * WSZ];              // 3.2 MB
__device__ __half g_h2[(size_t)NN * NRC];      // 33 MB
__device__ __half g_w1t[(size_t)NRWP * DD];    // 1.84 MB, [j][d] transposed fp16, zero-padded

__device__ __forceinline__ uint32_t smem_u32(const void* p) {
    uint32_t a;
    asm("{ .reg .u64 t; cvta.to.shared.u64 t, %1; cvt.u32.u64 %0, t; }" : "=r"(a) : "l"(p));
    return a;
}
__device__ __forceinline__ uint32_t pk_h2(float a, float b) {
    __half2 h = __floats2half2_rn(a, b);
    return *reinterpret_cast<uint32_t*>(&h);
}
__device__ __forceinline__ float2 upk_h2(uint32_t u) {
    __half2 h = *reinterpret_cast<__half2*>(&u);
    return __half22float2(h);
}
__device__ __forceinline__ void mma16816(float* d, const unsigned* a, const unsigned* b) {
    asm volatile("mma.sync.aligned.m16n8k16.row.col.f32.f16.f16.f32 "
                 "{%0,%1,%2,%3}, {%4,%5,%6,%7}, {%8,%9}, {%0,%1,%2,%3};\n"
                 : "+f"(d[0]), "+f"(d[1]), "+f"(d[2]), "+f"(d[3])
                 : "r"(a[0]), "r"(a[1]), "r"(a[2]), "r"(a[3]),
                   "r"(b[0]), "r"(b[1]));
}
__device__ __forceinline__ void ldsm_x4(unsigned* r, uint32_t addr) {
    asm volatile("ldmatrix.sync.aligned.m8n8.x4.shared.b16 {%0,%1,%2,%3}, [%4];"
                 : "=r"(r[0]), "=r"(r[1]), "=r"(r[2]), "=r"(r[3]) : "r"(addr));
}
#define CPA16(dst, src) asm volatile("cp.async.cg.shared.global [%0], [%1], 16;" :: "r"(dst), "l"(src))
#define CPC() asm volatile("cp.async.commit_group;" ::: "memory")
#define CPW() asm volatile("cp.async.wait_group 0;" ::: "memory")

// ============ launch 1: w1 transpose -> fp16 [j][d], zero-padded ============
__global__ void k_prepw(const float* __restrict__ w1) {
    int i = blockIdx.x * blockDim.x + threadIdx.x;
    if (i >= NRWP * DD) return;
    int j = i / DD, d = i - j * DD;
    float x = 0.f;
    if (j < NRW) x = w1[(j >> 4) * (DD * WSZ) + d * WSZ + (j & 15)];
    g_w1t[i] = __float2half_rn(x);
}
// ============ launch 2: zero h1 ============
__global__ void k_zero_h1() {
    int i = blockIdx.x * blockDim.x + threadIdx.x;
    if (i < NN * WSZ) g_h1[i] = 0.f;
}
// ============ launch 3: out = bias2 ============
__global__ void k_init_out(float* __restrict__ out, const float* __restrict__ b2) {
    int i = blockIdx.x * blockDim.x + threadIdx.x;
    if (i < NN * CC) out[i] = b2[i % CC];
}

// ============ launch 4: GEMM1 proj1[N,528](fp16) = emb[N,1600] @ W1cat ============
// BM=128, BN=192, BK=16, 256 threads, 2x4 warp grid (warp tile 64x48).
// smem stride 48B: 12r mod 32 is a permutation of r in [0,8) -> conflict-free.
#define GBM 128
#define GBN 192
#define ASTR 48
#define ABY (GBM * ASTR)   // 6144
#define BBY (GBN * ASTR)   // 9216

__global__ __launch_bounds__(256) void k_gemm1(const float* __restrict__ emb) {
    __shared__ __align__(16) char sA[2][ABY];
    __shared__ __align__(16) char sB[2][BBY];

    const int tid = threadIdx.x;
    const int warp = tid >> 5, lane = tid & 31;
    const int g = lane >> 2, tg = lane & 3;
    const int wm = warp & 1, wn = warp >> 1;
    const int row0 = blockIdx.y * GBM;
    const int col0 = blockIdx.x * GBN;

    // A fill: 128 rows x 16 fp16 per stage; each thread: 8 floats -> 16B
    const int arow = tid >> 1, ahalf = tid & 1;
    const int grow = row0 + arow;
    const bool aok = grow < NN;
    const float* asrc = emb + (size_t)grow * DD + ahalf * 8;
    char* adst_base = (char*)sA + arow * ASTR + ahalf * 16;

    // B fill via cp.async: 192 rows x 32B = 384 chunks of 16B
    const int brow0 = tid >> 1, bhalf = tid & 1;
    const int brow1 = (tid + 256) >> 1;
    const __half* bsrc0 = g_w1t + (size_t)(col0 + brow0) * DD + bhalf * 8;
    const __half* bsrc1 = g_w1t + (size_t)(col0 + brow1) * DD + bhalf * 8;
    const uint32_t sb0 = smem_u32(sB);
    const uint32_t bdst0 = sb0 + brow0 * ASTR + bhalf * 16;
    const uint32_t bdst1 = sb0 + brow1 * ASTR + bhalf * 16;

    float acc[4][6][4];
    #pragma unroll
    for (int i = 0; i < 4; i++)
        #pragma unroll
        for (int j = 0; j < 6; j++)
            #pragma unroll
            for (int q = 0; q < 4; q++) acc[i][j][q] = 0.f;

    float4 pa0, pa1;

    // ---- prologue: stage 0 ----
    pa0 = aok ? *(const float4*)asrc : make_float4(0, 0, 0, 0);
    pa1 = aok ? *(const float4*)(asrc + 4) : make_float4(0, 0, 0, 0);
    {
        uint4 u;
        u.x = pk_h2(pa0.x, pa0.y); u.y = pk_h2(pa0.z, pa0.w);
        u.z = pk_h2(pa1.x, pa1.y); u.w = pk_h2(pa1.z, pa1.w);
        *(uint4*)adst_base = u;
    }
    CPA16(bdst0, bsrc0);
    if (tid < 128) CPA16(bdst1, bsrc1);
    CPC();
    CPW();
    __syncthreads();

    const uint32_t aBase = smem_u32(sA) + (wm * 64 + (lane & 15)) * ASTR + (lane >> 4) * 16;

    const int T = DD / 16;  // 100
    for (int t = 0; t < T; t++) {
        const int cur = t & 1, nxt = cur ^ 1;
        if (t + 1 < T) {
            const int k0 = (t + 1) * 16;
            pa0 = aok ? *(const float4*)(asrc + k0) : make_float4(0, 0, 0, 0);
            pa1 = aok ? *(const float4*)(asrc + k0 + 4) : make_float4(0, 0, 0, 0);
            CPA16(bdst0 + nxt * BBY, (const char*)bsrc0 + k0 * 2);
            if (tid < 128) CPA16(bdst1 + nxt * BBY, (const char*)bsrc1 + k0 * 2);
            CPC();
        }

        // ---- compute on cur ----
        {
            unsigned af[4][4], bf[6][2];
            const uint32_t aB = aBase + cur * ABY;
            #pragma unroll
            for (int mi = 0; mi < 4; mi++)
                ldsm_x4(af[mi], aB + mi * (16 * ASTR));
            #pragma unroll
            for (int ni = 0; ni < 6; ni++) {
                const char* p = sB[cur] + (wn * 48 + ni * 8 + g) * ASTR + tg * 4;
                bf[ni][0] = *(const unsigned*)p;
                bf[ni][1] = *(const unsigned*)(p + 16);
            }
            #pragma unroll
            for (int mi = 0; mi < 4; mi++)
                #pragma unroll
                for (int ni = 0; ni < 6; ni++)
                    mma16816(acc[mi][ni], af[mi], bf[ni]);
        }

        if (t + 1 < T) {
            uint4 u;
            u.x = pk_h2(pa0.x, pa0.y); u.y = pk_h2(pa0.z, pa0.w);
            u.z = pk_h2(pa1.x, pa1.y); u.w = pk_h2(pa1.z, pa1.w);
            *(uint4*)(adst_base + nxt * ABY) = u;
            CPW();
            __syncthreads();
        }
    }

    // ---- epilogue: fp32 acc -> fp16 proj1 ----
    #pragma unroll
    for (int mi = 0; mi < 4; mi++) {
        #pragma unroll
        for (int ni = 0; ni < 6; ni++) {
            int r = row0 + wm * 64 + mi * 16 + g;
            int c = col0 + wn * 48 + ni * 8 + 2 * tg;
            if (c < NRW) {
                if (r < NN)
                    *(uint32_t*)&g_proj1[(size_t)r * NRW + c] = pk_h2(acc[mi][ni][0], acc[mi][ni][1]);
                if (r + 8 < NN)
                    *(uint32_t*)&g_proj1[(size_t)(r + 8) * NRW + c] = pk_h2(acc[mi][ni][2], acc[mi][ni][3]);
            }
        }
    }
}

// ============ launch 5: edge agg 1: h1[s] += val * proj1[o, p*16:+16] ============
__global__ void k_edge1(const float* __restrict__ ev, const int* __restrict__ es,
                        const int* __restrict__ ep, const int* __restrict__ eo, int E) {
    int idx = blockIdx.x * blockDim.x + threadIdx.x;
    int e = idx >> 1;
    if (e >= E) return;
    int q = idx & 1;
    int s = es[e], p = ep[e], o = eo[e];
    float v = ev[e];
    const uint4 m = *(const uint4*)(g_proj1 + (size_t)o * NRW + p * WSZ + q * 8);
    float2 f0 = upk_h2(m.x), f1 = upk_h2(m.y), f2 = upk_h2(m.z), f3 = upk_h2(m.w);
    float* dst = g_h1 + s * WSZ + q * 8;
    asm volatile("red.global.add.v4.f32 [%0], {%1,%2,%3,%4};"
                 :: "l"(dst), "f"(v * f0.x), "f"(v * f0.y), "f"(v * f1.x), "f"(v * f1.y) : "memory");
    asm volatile("red.global.add.v4.f32 [%0], {%1,%2,%3,%4};"
                 :: "l"(dst + 4), "f"(v * f2.x), "f"(v * f2.y), "f"(v * f3.x), "f"(v * f3.y) : "memory");
}

// ============ launch 6: layer-2 projection (bias1+relu fused) ============
// h2[n, j](fp16) = sum_w relu(h1[n,w]+b1[w]) * w2[j/10, w, j%10]
__global__ __launch_bounds__(128) void k_proj2(const float* __restrict__ w2,
                                               const float* __restrict__ b1) {
    int j = blockIdx.y * 128 + threadIdx.x;
    if (j >= NRC) return;
    int p = j / CC, c = j - p * CC;
    float wr[WSZ], br[WSZ];
    #pragma unroll
    for (int w = 0; w < WSZ; w++) {
        wr[w] = w2[p * (WSZ * CC) + w * CC + c];
        br[w] = __ldg(b1 + w);
    }
    int r0 = blockIdx.x * 256;
    int r1 = min(r0 + 256, NN);
    for (int row = r0; row < r1; row++) {
        const float4* hp = (const float4*)(g_h1 + row * WSZ);
        float4 h0 = __ldg(hp), h1v = __ldg(hp + 1), h2v = __ldg(hp + 2), h3 = __ldg(hp + 3);
        float a[16] = {h0.x, h0.y, h0.z, h0.w, h1v.x, h1v.y, h1v.z, h1v.w,
                       h2v.x, h2v.y, h2v.z, h2v.w, h3.x, h3.y, h3.z, h3.w};
        float acc = 0.f;
        #pragma unroll
        for (int w = 0; w < WSZ; w++) acc += fmaxf(a[w] + br[w], 0.f) * wr[w];
        g_h2[(size_t)row * NRC + j] = __float2half_rn(acc);
    }
}

// ============ launch 7: edge agg 2: out[s] += val * h2[o, p*10:+10] ============
__global__ void k_edge2(const float* __restrict__ ev, const int* __restrict__ es,
                        const int* __restrict__ ep, const int* __restrict__ eo,
                        float* __restrict__ out, int E) {
    int e = blockIdx.x * blockDim.x + threadIdx.x;
    if (e >= E) return;
    int s = es[e], p = ep[e], o = eo[e];
    float v = ev[e];
    const uint32_t* src = (const uint32_t*)(g_h2 + (size_t)o * NRC + p * CC);
    float* dst = out + s * CC;
    #pragma unroll
    for (int i = 0; i < 5; i++) {
        float2 f = upk_h2(src[i]);
        asm volatile("red.global.add.v2.f32 [%0], {%1,%2};"
                     :: "l"(dst + i * 2), "f"(v * f.x), "f"(v * f.y) : "memory");
    }
}

// ============ launch ============
extern "C" void kernel_launch(void* const* d_in, const int* in_sizes, int n_in,
                              void* d_out, int out_size) {
    const float* emb = (const float*)d_in[0];
    const float* w1  = (const float*)d_in[1];
    const float* b1  = (const float*)d_in[2];
    const float* w2  = (const float*)d_in[3];
    const float* b2  = (const float*)d_in[4];
    const float* ev  = (const float*)d_in[5];
    const int*   es  = (const int*)d_in[6];
    const int*   ep  = (const int*)d_in[7];
    const int*   eo  = (const int*)d_in[8];
    float* out = (float*)d_out;
    const int E = in_sizes[5];

    k_prepw<<<(NRWP * DD + 255) / 256, 256>>>(w1);
    k_zero_h1<<<(NN * WSZ + 255) / 256, 256>>>();
    k_init_out<<<(NN * CC + 255) / 256, 256>>>(out, b2);
    k_gemm1<<<dim3(3, (NN + GBM - 1) / GBM), 256>>>(emb);
    k_edge1<<<((long long)E * 2 + 255) / 256, 256>>>(ev, es, ep, eo, E);
    k_proj2<<<dim3((NN + 255) / 256, 3), 128>>>(w2, b1);
    k_edge2<<<(E + 255) / 256, 256>>>(ev, es, ep, eo, out, E);
}

// round 8
// speedup vs baseline: 1.2394x; 1.2394x over previous
#include <cuda_runtime.h>
#include <cuda_fp16.h>
#include <cstdint>

#define NN 50000
#define RR 33
#define DD 1600
#define WSZ 16
#define CC 10
#define NRW 528
#define NRC 330
#define NRWP 576

// ---- scratch (static device globals; allocation forbidden) ----
__device__ __half g_embh[(size_t)NN * DD];     // 160 MB, emb in fp16
__device__ __half g_proj1[(size_t)NN * NRW];   // 52.8 MB
__device__ float  g_h1[NN * WSZ];              // 3.2 MB
__device__ __half g_h2[(size_t)NN * NRC];      // 33 MB
__device__ __half g_w1t[(size_t)NRWP * DD];    // 1.84 MB, [j][d] fp16, zero-padded

__device__ __forceinline__ uint32_t smem_u32(const void* p) {
    uint32_t a;
    asm("{ .reg .u64 t; cvta.to.shared.u64 t, %1; cvt.u32.u64 %0, t; }" : "=r"(a) : "l"(p));
    return a;
}
__device__ __forceinline__ uint32_t pk_h2(float a, float b) {
    __half2 h = __floats2half2_rn(a, b);
    return *reinterpret_cast<uint32_t*>(&h);
}
__device__ __forceinline__ float2 upk_h2(uint32_t u) {
    __half2 h = *reinterpret_cast<__half2*>(&u);
    return __half22float2(h);
}
__device__ __forceinline__ void mma16816(float* d, const unsigned* a, const unsigned* b) {
    asm volatile("mma.sync.aligned.m16n8k16.row.col.f32.f16.f16.f32 "
                 "{%0,%1,%2,%3}, {%4,%5,%6,%7}, {%8,%9}, {%0,%1,%2,%3};\n"
                 : "+f"(d[0]), "+f"(d[1]), "+f"(d[2]), "+f"(d[3])
                 : "r"(a[0]), "r"(a[1]), "r"(a[2]), "r"(a[3]),
                   "r"(b[0]), "r"(b[1]));
}
__device__ __forceinline__ void ldsm_x4(unsigned* r, uint32_t addr) {
    asm volatile("ldmatrix.sync.aligned.m8n8.x4.shared.b16 {%0,%1,%2,%3}, [%4];"
                 : "=r"(r[0]), "=r"(r[1]), "=r"(r[2]), "=r"(r[3]) : "r"(addr));
}
#define CPA16Z(dst, src, n) \
    asm volatile("cp.async.cg.shared.global [%0], [%1], 16, %2;" :: "r"(dst), "l"(src), "r"(n))
#define CPC() asm volatile("cp.async.commit_group;" ::: "memory")
#define CPW2() asm volatile("cp.async.wait_group 2;" ::: "memory")

// ============ launch 1: w1 transpose -> fp16 [j][d], zero-padded ============
__global__ void k_prepw(const float* __restrict__ w1) {
    int i = blockIdx.x * blockDim.x + threadIdx.x;
    if (i >= NRWP * DD) return;
    int j = i / DD, d = i - j * DD;
    float x = 0.f;
    if (j < NRW) x = w1[(j >> 4) * (DD * WSZ) + d * WSZ + (j & 15)];
    g_w1t[i] = __float2half_rn(x);
}
// ============ launch 2: emb -> fp16 ============
__global__ void k_preph(const float* __restrict__ emb) {
    size_t i = (size_t)blockIdx.x * blockDim.x + threadIdx.x;  // 8 floats each
    size_t base = i * 8;
    if (base >= (size_t)NN * DD) return;
    float4 a = *(const float4*)(emb + base);
    float4 b = *(const float4*)(emb + base + 4);
    uint4 u;
    u.x = pk_h2(a.x, a.y); u.y = pk_h2(a.z, a.w);
    u.z = pk_h2(b.x, b.y); u.w = pk_h2(b.z, b.w);
    *(uint4*)(g_embh + base) = u;
}
// ============ launch 3: zero h1, out = bias2 ============
__global__ void k_init(float* __restrict__ out, const float* __restrict__ b2) {
    int i = blockIdx.x * blockDim.x + threadIdx.x;
    if (i < NN * WSZ) g_h1[i] = 0.f;
    if (i < NN * CC) out[i] = b2[i % CC];
}

// ============ launch 4: GEMM1 proj1[N,528](fp16) = embh[N,1600] @ W1cat ============
// BM=128, BN=96, BK=32, 256 thr, 2x4 warp grid (warp tile 64x24), 4-stage cp.async.
// smem row stride 80B -> 20r mod 32 permutation -> conflict-free ldmatrix/LDS.
#define GBM 128
#define GBN 96
#define ASTR 80
#define ABY (GBM * ASTR)          // 10240
#define BBY (GBN * ASTR)          // 7680
#define STG 4
#define GSM (STG * (ABY + BBY))   // 71680

extern __shared__ __align__(16) char smdyn[];

__global__ __launch_bounds__(256, 2) void k_gemm1() {
    const int tid = threadIdx.x;
    const int warp = tid >> 5, lane = tid & 31;
    const int g = lane >> 2, tg = lane & 3;
    const int wm = warp & 1, wn = warp >> 1;
    const int row0 = blockIdx.y * GBM;
    const int col0 = blockIdx.x * GBN;

    const uint32_t sA = smem_u32(smdyn);
    const uint32_t sB = sA + STG * ABY;

    // A fill: 128 rows x 64B -> 512 chunks of 16B, 2/thread
    const int arow = tid >> 1;
    const int aoff = (tid & 1) * 32;
    const int grow = row0 + arow;
    const uint32_t an = (grow < NN) ? 16u : 0u;
    const char* asrc = (const char*)(g_embh + (size_t)grow * DD) + aoff;
    const uint32_t adst = sA + arow * ASTR + aoff;

    // B fill: 96 rows x 64B -> 384 chunks, threads 0..191 take 2 each
    const int brow = tid >> 1;
    const int boff = (tid & 1) * 32;
    const bool bact = tid < 192;
    const char* bsrc = (const char*)(g_w1t + (size_t)(col0 + brow) * DD) + boff;
    const uint32_t bdst = sB + brow * ASTR + boff;

    float acc[4][3][4];
    #pragma unroll
    for (int i = 0; i < 4; i++)
        #pragma unroll
        for (int j = 0; j < 3; j++)
            #pragma unroll
            for (int q = 0; q < 4; q++) acc[i][j][q] = 0.f;

    const int T = DD / 32;  // 50

    // ---- prologue: stages 0..2 ----
    #pragma unroll
    for (int st = 0; st < STG - 1; st++) {
        const int kb = st * 64;  // bytes into the row (32 halves = 64B)
        CPA16Z(adst + st * ABY, asrc + kb, an);
        CPA16Z(adst + st * ABY + 16, asrc + kb + 16, an);
        if (bact) {
            CPA16Z(bdst + st * BBY, bsrc + kb, 16u);
            CPA16Z(bdst + st * BBY + 16, bsrc + kb + 16, 16u);
        }
        CPC();
    }

    const uint32_t aBase = sA + (wm * 64 + (lane & 15)) * ASTR + (lane >> 4) * 16;

    for (int t = 0; t < T; t++) {
        CPW2();
        __syncthreads();

        // prefetch stage t+3
        if (t + STG - 1 < T) {
            const int st = (t + STG - 1) & (STG - 1);
            const int kb = (t + STG - 1) * 64;
            CPA16Z(adst + st * ABY, asrc + kb, an);
            CPA16Z(adst + st * ABY + 16, asrc + kb + 16, an);
            if (bact) {
                CPA16Z(bdst + st * BBY, bsrc + kb, 16u);
                CPA16Z(bdst + st * BBY + 16, bsrc + kb + 16, 16u);
            }
        }
        CPC();

        // compute stage t
        const int cs = t & (STG - 1);
        const uint32_t aB = aBase + cs * ABY;
        const uint32_t bRow = sB + cs * BBY;
        #pragma unroll
        for (int s = 0; s < 2; s++) {
            unsigned af[4][4], bf[3][2];
            #pragma unroll
            for (int mi = 0; mi < 4; mi++)
                ldsm_x4(af[mi], aB + mi * (16 * ASTR) + s * 32);
            #pragma unroll
            for (int ni = 0; ni < 3; ni++) {
                const uint32_t p = bRow + (wn * 24 + ni * 8 + g) * ASTR + s * 32 + tg * 4;
                asm volatile("ld.shared.b32 %0, [%1];" : "=r"(bf[ni][0]) : "r"(p));
                asm volatile("ld.shared.b32 %0, [%1];" : "=r"(bf[ni][1]) : "r"(p + 16));
            }
            #pragma unroll
            for (int mi = 0; mi < 4; mi++)
                #pragma unroll
                for (int ni = 0; ni < 3; ni++)
                    mma16816(acc[mi][ni], af[mi], bf[ni]);
        }
    }

    // ---- epilogue: fp32 acc -> fp16 proj1 ----
    #pragma unroll
    for (int mi = 0; mi < 4; mi++) {
        #pragma unroll
        for (int ni = 0; ni < 3; ni++) {
            int r = row0 + wm * 64 + mi * 16 + g;
            int c = col0 + wn * 24 + ni * 8 + 2 * tg;
            if (c < NRW) {
                if (r < NN)
                    *(uint32_t*)&g_proj1[(size_t)r * NRW + c] = pk_h2(acc[mi][ni][0], acc[mi][ni][1]);
                if (r + 8 < NN)
                    *(uint32_t*)&g_proj1[(size_t)(r + 8) * NRW + c] = pk_h2(acc[mi][ni][2], acc[mi][ni][3]);
            }
        }
    }
}

// ============ launch 5: edge agg 1: h1[s] += val * proj1[o, p*16:+16] ============
__global__ void k_edge1(const float* __restrict__ ev, const int* __restrict__ es,
                        const int* __restrict__ ep, const int* __restrict__ eo, int E) {
    int idx = blockIdx.x * blockDim.x + threadIdx.x;
    int e = idx >> 1;
    if (e >= E) return;
    int q = idx & 1;
    int s = es[e], p = ep[e], o = eo[e];
    float v = ev[e];
    const uint4 m = *(const uint4*)(g_proj1 + (size_t)o * NRW + p * WSZ + q * 8);
    float2 f0 = upk_h2(m.x), f1 = upk_h2(m.y), f2 = upk_h2(m.z), f3 = upk_h2(m.w);
    float* dst = g_h1 + s * WSZ + q * 8;
    asm volatile("red.global.add.v4.f32 [%0], {%1,%2,%3,%4};"
                 :: "l"(dst), "f"(v * f0.x), "f"(v * f0.y), "f"(v * f1.x), "f"(v * f1.y) : "memory");
    asm volatile("red.global.add.v4.f32 [%0], {%1,%2,%3,%4};"
                 :: "l"(dst + 4), "f"(v * f2.x), "f"(v * f2.y), "f"(v * f3.x), "f"(v * f3.y) : "memory");
}

// ============ launch 6: layer-2 projection (bias1+relu fused) ============
__global__ __launch_bounds__(128) void k_proj2(const float* __restrict__ w2,
                                               const float* __restrict__ b1) {
    int j = blockIdx.y * 128 + threadIdx.x;
    if (j >= NRC) return;
    int p = j / CC, c = j - p * CC;
    float wr[WSZ], br[WSZ];
    #pragma unroll
    for (int w = 0; w < WSZ; w++) {
        wr[w] = w2[p * (WSZ * CC) + w * CC + c];
        br[w] = __ldg(b1 + w);
    }
    int r0 = blockIdx.x * 256;
    int r1 = min(r0 + 256, NN);
    for (int row = r0; row < r1; row++) {
        const float4* hp = (const float4*)(g_h1 + row * WSZ);
        float4 h0 = __ldg(hp), h1v = __ldg(hp + 1), h2v = __ldg(hp + 2), h3 = __ldg(hp + 3);
        float a[16] = {h0.x, h0.y, h0.z, h0.w, h1v.x, h1v.y, h1v.z, h1v.w,
                       h2v.x, h2v.y, h2v.z, h2v.w, h3.x, h3.y, h3.z, h3.w};
        float acc = 0.f;
        #pragma unroll
        for (int w = 0; w < WSZ; w++) acc += fmaxf(a[w] + br[w], 0.f) * wr[w];
        g_h2[(size_t)row * NRC + j] = __float2half_rn(acc);
    }
}

// ============ launch 7: edge agg 2: out[s] += val * h2[o, p*10:+10] ============
__global__ void k_edge2(const float* __restrict__ ev, const int* __restrict__ es,
                        const int* __restrict__ ep, const int* __restrict__ eo,
                        float* __restrict__ out, int E) {
    int e = blockIdx.x * blockDim.x + threadIdx.x;
    if (e >= E) return;
    int s = es[e], p = ep[e], o = eo[e];
    float v = ev[e];
    const uint32_t* src = (const uint32_t*)(g_h2 + (size_t)o * NRC + p * CC);
    float* dst = out + s * CC;
    #pragma unroll
    for (int i = 0; i < 5; i++) {
        float2 f = upk_h2(src[i]);
        asm volatile("red.global.add.v2.f32 [%0], {%1,%2};"
                     :: "l"(dst + i * 2), "f"(v * f.x), "f"(v * f.y) : "memory");
    }
}

// ============ launch ============
extern "C" void kernel_launch(void* const* d_in, const int* in_sizes, int n_in,
                              void* d_out, int out_size) {
    const float* emb = (const float*)d_in[0];
    const float* w1  = (const float*)d_in[1];
    const float* b1  = (const float*)d_in[2];
    const float* w2  = (const float*)d_in[3];
    const float* b2  = (const float*)d_in[4];
    const float* ev  = (const float*)d_in[5];
    const int*   es  = (const int*)d_in[6];
    const int*   ep  = (const int*)d_in[7];
    const int*   eo  = (const int*)d_in[8];
    float* out = (float*)d_out;
    const int E = in_sizes[5];

    cudaFuncSetAttribute(k_gemm1, cudaFuncAttributeMaxDynamicSharedMemorySize, GSM);

    k_prepw<<<(NRWP * DD + 255) / 256, 256>>>(w1);
    k_preph<<<(int)(((size_t)NN * DD / 8 + 255) / 256), 256>>>(emb);
    k_init<<<(NN * WSZ + 255) / 256, 256>>>(out, b2);
    k_gemm1<<<dim3(6, (NN + GBM - 1) / GBM), 256, GSM>>>();
    k_edge1<<<((long long)E * 2 + 255) / 256, 256>>>(ev, es, ep, eo, E);
    k_proj2<<<dim3((NN + 255) / 256, 3), 128>>>(w2, b1);
    k_edge2<<<(E + 255) / 256, 256>>>(ev, es, ep, eo, out, E);
}

// round 12
// speedup vs baseline: 1.2932x; 1.0434x over previous
#include <cuda_runtime.h>
#include <cuda_fp16.h>
#include <cstdint>

#define NN 50000
#define RR 33
#define DD 1600
#define WSZ 16
#define CC 10
#define NRW 528
#define NRC 330
#define NRWP 576

// ---- scratch (static device globals; allocation forbidden) ----
__device__ __half g_embh[(size_t)NN * DD];     // 160 MB, emb in fp16
__device__ __half g_proj1[(size_t)NN * NRW];   // 52.8 MB
__device__ float  g_h1[NN * WSZ];              // 3.2 MB
__device__ __half g_h2[(size_t)NN * NRC];      // 33 MB
__device__ __half g_w1t[(size_t)NRWP * DD];    // 1.84 MB, [j][d] fp16, zero-padded

__device__ __forceinline__ uint32_t smem_u32(const void* p) {
    uint32_t a;
    asm("{ .reg .u64 t; cvta.to.shared.u64 t, %1; cvt.u32.u64 %0, t; }" : "=r"(a) : "l"(p));
    return a;
}
__device__ __forceinline__ uint32_t pk_h2(float a, float b) {
    __half2 h = __floats2half2_rn(a, b);
    return *reinterpret_cast<uint32_t*>(&h);
}
__device__ __forceinline__ float2 upk_h2(uint32_t u) {
    __half2 h = *reinterpret_cast<__half2*>(&u);
    return __half22float2(h);
}
__device__ __forceinline__ void mma16816(float* d, const unsigned* a, const unsigned* b) {
    asm volatile("mma.sync.aligned.m16n8k16.row.col.f32.f16.f16.f32 "
                 "{%0,%1,%2,%3}, {%4,%5,%6,%7}, {%8,%9}, {%0,%1,%2,%3};\n"
                 : "+f"(d[0]), "+f"(d[1]), "+f"(d[2]), "+f"(d[3])
                 : "r"(a[0]), "r"(a[1]), "r"(a[2]), "r"(a[3]),
                   "r"(b[0]), "r"(b[1]));
}
__device__ __forceinline__ void ldsm_x4(unsigned* r, uint32_t addr) {
    asm volatile("ldmatrix.sync.aligned.m8n8.x4.shared.b16 {%0,%1,%2,%3}, [%4];"
                 : "=r"(r[0]), "=r"(r[1]), "=r"(r[2]), "=r"(r[3]) : "r"(addr));
}
#define CPA16Z(dst, src, n) \
    asm volatile("cp.async.cg.shared.global [%0], [%1], 16, %2;" :: "r"(dst), "l"(src), "r"(n))
#define CPC() asm volatile("cp.async.commit_group;" ::: "memory")
#define CPW2() asm volatile("cp.async.wait_group 2;" ::: "memory")

// ============ launch 1: w1 transpose->fp16 + zero h1 + out=bias2 ============
__global__ void k_prep(const float* __restrict__ w1, const float* __restrict__ b2,
                       float* __restrict__ out) {
    int i = blockIdx.x * blockDim.x + threadIdx.x;
    if (i < NRWP * DD) {
        int j = i / DD, d = i - j * DD;
        float x = 0.f;
        if (j < NRW) x = w1[(j >> 4) * (DD * WSZ) + d * WSZ + (j & 15)];
        g_w1t[i] = __float2half_rn(x);
    }
    if (i < NN * WSZ) g_h1[i] = 0.f;
    if (i < NN * CC) out[i] = b2[i % CC];
}
// ============ launch 2: emb -> fp16 ============
__global__ void k_preph(const float* __restrict__ emb) {
    size_t i = (size_t)blockIdx.x * blockDim.x + threadIdx.x;  // 8 floats each
    size_t base = i * 8;
    if (base >= (size_t)NN * DD) return;
    float4 a = *(const float4*)(emb + base);
    float4 b = *(const float4*)(emb + base + 4);
    uint4 u;
    u.x = pk_h2(a.x, a.y); u.y = pk_h2(a.z, a.w);
    u.z = pk_h2(b.x, b.y); u.w = pk_h2(b.z, b.w);
    *(uint4*)(g_embh + base) = u;
}

// ============ launch 3: GEMM1 proj1[N,528](fp16) = embh[N,1600] @ W1cat ============
// BM=128, BN=96, BK=32, 256 thr, 2x4 warp grid (warp tile 64x24), 4-stage cp.async.
// smem row stride 80B -> 20r mod 32 permutation -> conflict-free ldmatrix.
// Identical to the validated round-8 kernel EXCEPT B fragments now come from
// 2 ldmatrix.x4 per s-step instead of 12 scalar LDS (same fragment values).
#define GBM 128
#define GBN 96
#define ASTR 80
#define ABY (GBM * ASTR)          // 10240
#define BBY (GBN * ASTR)          // 7680
#define STG 4
#define GSM (STG * (ABY + BBY))   // 71680

extern __shared__ __align__(16) char smdyn[];

__global__ __launch_bounds__(256, 2) void k_gemm1() {
    const int tid = threadIdx.x;
    const int warp = tid >> 5, lane = tid & 31;
    const int wm = warp & 1, wn = warp >> 1;
    const int row0 = blockIdx.y * GBM;
    const int col0 = blockIdx.x * GBN;

    const uint32_t sA = smem_u32(smdyn);
    const uint32_t sB = sA + STG * ABY;

    // A fill: 128 rows x 64B -> 512 chunks of 16B, 2/thread
    const int arow = tid >> 1;
    const int aoff = (tid & 1) * 32;
    const int grow = row0 + arow;
    const uint32_t an = (grow < NN) ? 16u : 0u;
    const int growc = (grow < NN) ? grow : (NN - 1);
    const char* asrc = (const char*)(g_embh + (size_t)growc * DD) + aoff;
    const uint32_t adst = sA + arow * ASTR + aoff;

    // B fill: 96 rows x 64B -> 384 chunks, threads 0..191 take 2 each
    const int brow = tid >> 1;
    const int boff = (tid & 1) * 32;
    const bool bact = tid < 192;
    const int browc = bact ? brow : 0;
    const char* bsrc = (const char*)(g_w1t + (size_t)(col0 + browc) * DD) + boff;
    const uint32_t bdst = sB + browc * ASTR + boff;

    float acc[4][3][4];
    #pragma unroll
    for (int i = 0; i < 4; i++)
        #pragma unroll
        for (int j = 0; j < 3; j++)
            #pragma unroll
            for (int q = 0; q < 4; q++) acc[i][j][q] = 0.f;

    const int T = DD / 32;  // 50

    // ---- prologue: stages 0..2 ----
    #pragma unroll
    for (int st = 0; st < STG - 1; st++) {
        const int kb = st * 64;
        CPA16Z(adst + st * ABY, asrc + kb, an);
        CPA16Z(adst + st * ABY + 16, asrc + kb + 16, an);
        if (bact) {
            CPA16Z(bdst + st * BBY, bsrc + kb, 16u);
            CPA16Z(bdst + st * BBY + 16, bsrc + kb + 16, 16u);
        }
        CPC();
    }

    // fragment read bases
    const uint32_t aBase = sA + (wm * 64 + (lane & 15)) * ASTR + (lane >> 4) * 16;
    // B ldmatrix bases: ldsm1 -> n-octets 0,1 (k-low/high interleaved), ldsm2 -> n-octet 2 (dup)
    const uint32_t bB1 = sB + (wn * 24 + ((lane >> 4) << 3) + (lane & 7)) * ASTR
                            + ((lane >> 3) & 1) * 16;
    const uint32_t bB2 = sB + (wn * 24 + 16 + (lane & 7)) * ASTR
                            + ((lane >> 3) & 1) * 16;

    for (int t = 0; t < T; t++) {
        CPW2();
        __syncthreads();

        // prefetch stage t+3
        if (t + STG - 1 < T) {
            const int st = (t + STG - 1) & (STG - 1);
            const int kb = (t + STG - 1) * 64;
            CPA16Z(adst + st * ABY, asrc + kb, an);
            CPA16Z(adst + st * ABY + 16, asrc + kb + 16, an);
            if (bact) {
                CPA16Z(bdst + st * BBY, bsrc + kb, 16u);
                CPA16Z(bdst + st * BBY + 16, bsrc + kb + 16, 16u);
            }
        }
        CPC();

        // compute stage t
        const int cs = t & (STG - 1);
        const uint32_t aB = aBase + cs * ABY;
        const uint32_t b1B = bB1 + cs * BBY;
        const uint32_t b2B = bB2 + cs * BBY;
        #pragma unroll
        for (int s = 0; s < 2; s++) {
            unsigned af[4][4], b1[4], b2[4];
            #pragma unroll
            for (int mi = 0; mi < 4; mi++)
                ldsm_x4(af[mi], aB + mi * (16 * ASTR) + s * 32);
            ldsm_x4(b1, b1B + s * 32);   // r0,r1 = ni0 k-low/high; r2,r3 = ni1
            ldsm_x4(b2, b2B + s * 32);   // r0,r1 = ni2; r2,r3 dup (ignored)
            #pragma unroll
            for (int mi = 0; mi < 4; mi++) {
                mma16816(acc[mi][0], af[mi], b1 + 0);
                mma16816(acc[mi][1], af[mi], b1 + 2);
                mma16816(acc[mi][2], af[mi], b2 + 0);
            }
        }
    }

    // ---- epilogue: fp32 acc -> fp16 proj1 ----
    const int g = lane >> 2, tg = lane & 3;
    #pragma unroll
    for (int mi = 0; mi < 4; mi++) {
        #pragma unroll
        for (int ni = 0; ni < 3; ni++) {
            int r = row0 + wm * 64 + mi * 16 + g;
            int c = col0 + wn * 24 + ni * 8 + 2 * tg;
            if (c < NRW) {
                if (r < NN)
                    *(uint32_t*)&g_proj1[(size_t)r * NRW + c] = pk_h2(acc[mi][ni][0], acc[mi][ni][1]);
                if (r + 8 < NN)
                    *(uint32_t*)&g_proj1[(size_t)(r + 8) * NRW + c] = pk_h2(acc[mi][ni][2], acc[mi][ni][3]);
            }
        }
    }
}

// ============ launch 4 (profiled): edge agg 1: h1[s] += val * proj1[o, p*16:+16] ============
__global__ void k_edge1(const float* __restrict__ ev, const int* __restrict__ es,
                        const int* __restrict__ ep, const int* __restrict__ eo, int E) {
    int idx = blockIdx.x * blockDim.x + threadIdx.x;
    int e = idx >> 1;
    if (e >= E) return;
    int q = idx & 1;
    int s = es[e], p = ep[e], o = eo[e];
    float v = ev[e];
    const uint4 m = *(const uint4*)(g_proj1 + (size_t)o * NRW + p * WSZ + q * 8);
    float2 f0 = upk_h2(m.x), f1 = upk_h2(m.y), f2 = upk_h2(m.z), f3 = upk_h2(m.w);
    float* dst = g_h1 + s * WSZ + q * 8;
    asm volatile("red.global.add.v4.f32 [%0], {%1,%2,%3,%4};"
                 :: "l"(dst), "f"(v * f0.x), "f"(v * f0.y), "f"(v * f1.x), "f"(v * f1.y) : "memory");
    asm volatile("red.global.add.v4.f32 [%0], {%1,%2,%3,%4};"
                 :: "l"(dst + 4), "f"(v * f2.x), "f"(v * f2.y), "f"(v * f3.x), "f"(v * f3.y) : "memory");
}

// ============ launch 5: layer-2 projection (bias1+relu fused) ============
__global__ __launch_bounds__(128) void k_proj2(const float* __restrict__ w2,
                                               const float* __restrict__ b1) {
    int j = blockIdx.y * 128 + threadIdx.x;
    if (j >= NRC) return;
    int p = j / CC, c = j - p * CC;
    float wr[WSZ], br[WSZ];
    #pragma unroll
    for (int w = 0; w < WSZ; w++) {
        wr[w] = w2[p * (WSZ * CC) + w * CC + c];
        br[w] = __ldg(b1 + w);
    }
    int r0 = blockIdx.x * 256;
    int r1 = min(r0 + 256, NN);
    for (int row = r0; row < r1; row++) {
        const float4* hp = (const float4*)(g_h1 + row * WSZ);
        float4 h0 = __ldg(hp), h1v = __ldg(hp + 1), h2v = __ldg(hp + 2), h3 = __ldg(hp + 3);
        float a[16] = {h0.x, h0.y, h0.z, h0.w, h1v.x, h1v.y, h1v.z, h1v.w,
                       h2v.x, h2v.y, h2v.z, h2v.w, h3.x, h3.y, h3.z, h3.w};
        float acc = 0.f;
        #pragma unroll
        for (int w = 0; w < WSZ; w++) acc += fmaxf(a[w] + br[w], 0.f) * wr[w];
        g_h2[(size_t)row * NRC + j] = __float2half_rn(acc);
    }
}

// ============ launch 6: edge agg 2: out[s] += val * h2[o, p*10:+10] ============
__global__ void k_edge2(const float* __restrict__ ev, const int* __restrict__ es,
                        const int* __restrict__ ep, const int* __restrict__ eo,
                        float* __restrict__ out, int E) {
    int e = blockIdx.x * blockDim.x + threadIdx.x;
    if (e >= E) return;
    int s = es[e], p = ep[e], o = eo[e];
    float v = ev[e];
    const uint32_t* src = (const uint32_t*)(g_h2 + (size_t)o * NRC + p * CC);
    float* dst = out + s * CC;
    #pragma unroll
    for (int i = 0; i < 5; i++) {
        float2 f = upk_h2(src[i]);
        asm volatile("red.global.add.v2.f32 [%0], {%1,%2};"
                     :: "l"(dst + i * 2), "f"(v * f.x), "f"(v * f.y) : "memory");
    }
}

// ============ launch ============
extern "C" void kernel_launch(void* const* d_in, const int* in_sizes, int n_in,
                              void* d_out, int out_size) {
    const float* emb = (const float*)d_in[0];
    const float* w1  = (const float*)d_in[1];
    const float* b1  = (const float*)d_in[2];
    const float* w2  = (const float*)d_in[3];
    const float* b2  = (const float*)d_in[4];
    const float* ev  = (const float*)d_in[5];
    const int*   es  = (const int*)d_in[6];
    const int*   ep  = (const int*)d_in[7];
    const int*   eo  = (const int*)d_in[8];
    float* out = (float*)d_out;
    const int E = in_sizes[5];

    cudaFuncSetAttribute(k_gemm1, cudaFuncAttributeMaxDynamicSharedMemorySize, GSM);

    k_prep<<<(NRWP * DD + 255) / 256, 256>>>(w1, b2, out);
    k_preph<<<(int)(((size_t)NN * DD / 8 + 255) / 256), 256>>>(emb);
    k_gemm1<<<dim3(6, (NN + GBM - 1) / GBM), 256, GSM>>>();
    k_edge1<<<((long long)E * 2 + 255) / 256, 256>>>(ev, es, ep, eo, E);
    k_proj2<<<dim3((NN + 255) / 256, 3), 128>>>(w2, b1);
    k_edge2<<<(E + 255) / 256, 256>>>(ev, es, ep, eo, out, E);
}